// round 16
// baseline (speedup 1.0000x reference)
#include <cuda_runtime.h>

#define L2E  1.4426950408889634f
#define LN2  0.6931471805599453f
#define BIGQ (-(1 << 27))

typedef unsigned long long u64;

__device__ __forceinline__ float ex2f_(float x){ float r; asm("ex2.approx.f32 %0, %1;" : "=f"(r) : "f"(x)); return r; }
__device__ __forceinline__ float lg2f_(float x){ float r; asm("lg2.approx.f32 %0, %1;" : "=f"(r) : "f"(x)); return r; }
__device__ __forceinline__ u64 pk2(float lo, float hi){ u64 r; asm("mov.b64 %0,{%1,%2};" : "=l"(r) : "f"(lo), "f"(hi)); return r; }
__device__ __forceinline__ void upk2(float& lo, float& hi, u64 v){ asm("mov.b64 {%0,%1},%2;" : "=f"(lo), "=f"(hi) : "l"(v)); }
__device__ __forceinline__ u64 fma2(u64 a, u64 b, u64 c){ u64 r; asm("fma.rn.f32x2 %0,%1,%2,%3;" : "=l"(r) : "l"(a), "l"(b), "l"(c)); return r; }

// exact e * 2^max(dq, -126), e in [1,2), dq <= 0 (IADD3 + IMNMX + IMAD)
__device__ __forceinline__ float scl_(float e, int dq){
    int d = dq < -126 ? -126 : dq;
    return __uint_as_float(__float_as_uint(e) + (unsigned)d * 8388608u);
}

// One warp = FOUR (a,b) pairs chained in anti-phase (+128 steps each), 4 rows/thread,
// 1 warp per SMSP (128 blocks x 128 threads). Weight-domain DP: w = e*2^q.
// This round: FFMA2 dot with zero packing overhead — Y rows stored as packed
// 12-float chunks [y0..3][y4..7][nyq,0,0,0], loaded straight into u64 register
// pairs; seeds pre-packed at init. 5 FFMA2 replace FADD + 8 FFMA per cell.
__global__ __launch_bounds__(128, 1)
void sdtw_kernel(const float* __restrict__ X, const float* __restrict__ Y,
                 float* __restrict__ out)
{
    // 4 tiles, 1536 floats each. Row j of tile t:
    //   chunk c (c=0,1,2) word w at sy[t*1536 + (j&3)*384 + c*128 + (j>>2)*4 + w]
    //   chunk0/1 = y[0..7]; chunk2 = (-L2E*|y|^2, 0, 0, 0)
    __shared__ __align__(16) float sy[4 * 1536];

    const int tid  = threadIdx.x;
    const int lane = tid & 31;
    const int wid  = tid >> 5;

    const int b0 = (blockIdx.x & 3) * 4;
    const int a  = (blockIdx.x >> 2) * 4 + wid;

    for (int rep = 0; rep < 4; ++rep) {
        int gr   = tid + rep * 128;
        int tile = gr >> 7;
        int j    = gr & 127;
        const float* yrow = Y + (size_t)(b0 + tile) * 1024 + j * 8;
        float sq = 0.f;
        int base = tile * 1536 + (j & 3) * 384 + (j >> 2) * 4;
        #pragma unroll
        for (int k = 0; k < 8; ++k) {
            float vv = yrow[k];
            sq = fmaf(vv, vv, sq);
            sy[base + (k >> 2) * 128 + (k & 3)] = vv;
        }
        sy[base + 256 + 0] = sq * (-L2E);
        sy[base + 256 + 1] = 0.f;
        sy[base + 256 + 2] = 0.f;
        sy[base + 256 + 3] = 0.f;
    }

    // X packed once: xs2 = +2*L2E*x pairs; nsq2[s] = (-L2E*|x|^2, 0); xs21 = (1,0)
    u64 xs2[4][4];
    u64 nsq2[4];
    const u64 xs21 = pk2(1.0f, 0.0f);
    {
        const float* xp = X + (size_t)a * 1024 + lane * 32;
        #pragma unroll
        for (int s = 0; s < 4; ++s) {
            float acc = 0.f;
            #pragma unroll
            for (int kp = 0; kp < 4; ++kp) {
                float f0 = xp[s * 8 + 2 * kp];
                float f1 = xp[s * 8 + 2 * kp + 1];
                acc = fmaf(f0, f0, fmaf(f1, f1, acc));
                xs2[s][kp] = pk2(f0 * (2.0f * L2E), f1 * (2.0f * L2E));
            }
            nsq2[s] = pk2(acc * (-L2E), 0.f);
        }
    }
    __syncthreads();

    // DP state: mantissa e in [1,2), exponent q (int). Masked == q very negative.
    float e[2][4];
    int   q[2][4];
    #pragma unroll
    for (int s = 0; s < 4; ++s) {
        e[0][s] = 1.0f; e[1][s] = 1.0f;
        q[0][s] = BIGQ; q[1][s] = BIGQ;
    }

    // Y register pipeline: buffer (p)&3 holds row ja0(p) = p - 4*lane,
    // as 4 packed y-pairs + 1 packed (nyq,0) pair.
    u64 yp2[4][4];
    u64 ynq[4];
    #pragma unroll
    for (int b = 0; b < 4; ++b) {
        ynq[b] = 0ull;
        #pragma unroll
        for (int kp = 0; kp < 4; ++kp) yp2[b][kp] = 0ull;
    }

    const int lane4 = lane * 4;

    // prologue: buffer 0 <- row ja0(p=0) = -lane4 (wrapped; real only for lane 0)
    {
        unsigned jb = (unsigned)(-lane4) & 511u;
        int A = (int)(jb >> 7) * 1536 + (int)(jb & 3u) * 384 + (int)((jb >> 2) & 31u) * 4;
        ulonglong2 u0 = *reinterpret_cast<const ulonglong2*>(&sy[A]);
        ulonglong2 u1 = *reinterpret_cast<const ulonglong2*>(&sy[A + 128]);
        yp2[0][0] = u0.x; yp2[0][1] = u0.y; yp2[0][2] = u1.x; yp2[0][3] = u1.y;
        ynq[0] = *reinterpret_cast<const u64*>(&sy[A + 256]);
    }

    // shuffle pipeline: shC = shfl of slot3 from step p-1 (this step's s=0 "up"),
    //                   shP = shfl of slot3 from step p-2 (this step's s=0 "diag").
    float shCe = 1.0f, shPe = 1.0f;
    int   shCq = BIGQ, shPq = BIGQ;

    const int outA = a * 16 + b0;
    const bool storeLane = (lane == 31);

    // one DP cell: softmin(aligned add) * ex2(distance via 5 FFMA2), exact split
    #define CELL(S, BUF, EU, QU, EL, QL, ED, QD, WI)                                   \
    {                                                                                   \
        int qm = max(max((QU), (QL)), (QD));                                            \
        float sum = (scl_((EU), (QU) - qm) + scl_((EL), (QL) - qm))                     \
                  + scl_((ED), (QD) - qm);                                              \
        u64 acc2 = fma2(xs2[S][0], yp2[BUF][0], nsq2[S]);                               \
        acc2 = fma2(xs2[S][1], yp2[BUF][1], acc2);                                      \
        acc2 = fma2(xs2[S][2], yp2[BUF][2], acc2);                                      \
        acc2 = fma2(xs2[S][3], yp2[BUF][3], acc2);                                      \
        acc2 = fma2(xs21, ynq[BUF], acc2);                                              \
        float lo_, hi_; upk2(lo_, hi_, acc2);                                           \
        float w = sum * ex2f_(lo_ + hi_);                                               \
        unsigned wb = __float_as_uint(w);                                               \
        q[WI][S] = qm - 127 + (int)(wb >> 23);                                          \
        e[WI][S] = __uint_as_float((wb & 0x007FFFFFu) | 0x3F800000u);                   \
    }

    for (int p0 = 0; p0 < 640; p0 += 4) {
        const int j0      = p0 - lane4;
        const unsigned jc = (unsigned)j0 & 511u;
        const unsigned jn = (unsigned)(j0 + 4) & 511u;
        const int base0   = (int)(jc >> 7) * 1536 + (int)((jc >> 2) & 31u) * 4;
        const int base1   = (int)(jn >> 7) * 1536 + (int)((jn >> 2) & 31u) * 4;
        const bool bj0    = ((jc & 127u) == 0u);   // per-pair j==0 boundary: fires only at s==u
        const bool harv   = ((p0 & 127) == 124) && (p0 >= 252) && storeLane;
        const int  hIdx   = outA + ((p0 - 252) >> 7);

        #pragma unroll
        for (int u = 0; u < 4; ++u) {
            const int wIdx = u & 1;
            const int rIdx = wIdx ^ 1;

            // ---- slot 3 FIRST (reads prev2 q[wIdx][2] before slot 2 overwrites it) ----
            {
                float el = e[rIdx][3], ed = e[wIdx][2];
                int   ql, qd;
                if (u == 3) { ql = bj0 ? BIGQ : q[rIdx][3];  qd = bj0 ? BIGQ : q[wIdx][2]; }
                else        { ql = q[rIdx][3];               qd = q[wIdx][2]; }
                CELL(3, (u + 1) & 3, e[rIdx][2], q[rIdx][2], el, ql, ed, qd, wIdx)
            }

            // ---- shuffle slot3 for NEXT step, issued ~100 instr before its consumer ----
            const float shNe = __shfl_up_sync(0xffffffffu, e[wIdx][3], 1);
            const int   shNq = __shfl_up_sync(0xffffffffu, q[wIdx][3], 1);

            // ---- refill buffer (u+1)&3 (slot 3, its only pending reader, is done) ----
            {
                const int A = (u < 3) ? (base0 + (u + 1) * 384) : base1;
                const int b = (u + 1) & 3;
                ulonglong2 u0 = *reinterpret_cast<const ulonglong2*>(&sy[A]);
                ulonglong2 u1 = *reinterpret_cast<const ulonglong2*>(&sy[A + 128]);
                yp2[b][0] = u0.x; yp2[b][1] = u0.y; yp2[b][2] = u1.x; yp2[b][3] = u1.y;
                ynq[b] = *reinterpret_cast<const u64*>(&sy[A + 256]);
            }

            // ---- slots 2, 1 ----
            #pragma unroll
            for (int s = 2; s >= 1; --s) {
                float el = e[rIdx][s], ed = e[wIdx][s - 1];
                int   ql, qd;
                if (s == u) { ql = bj0 ? BIGQ : q[rIdx][s];  qd = bj0 ? BIGQ : q[wIdx][s - 1]; }
                else        { ql = q[rIdx][s];               qd = q[wIdx][s - 1]; }
                CELL(s, (u - s) & 3, e[rIdx][s - 1], q[rIdx][s - 1], el, ql, ed, qd, wIdx)
            }

            // ---- slot 0 (consumes the shuffles issued LAST step: shC/shP) ----
            {
                float eu = shCe, el, ed;
                int   qu = (lane == 0) ? BIGQ : shCq, ql, qd;
                if (u == 0) {
                    el = e[rIdx][0];  ql = bj0 ? BIGQ : q[rIdx][0];
                    if (lane == 0) { ed = 1.0f;  qd = bj0 ? 0 : BIGQ; }   // corner seed of each pair
                    else           { ed = shPe;  qd = bj0 ? BIGQ : shPq; }
                } else {
                    el = e[rIdx][0];  ql = q[rIdx][0];
                    ed = shPe;        qd = (lane == 0) ? BIGQ : shPq;
                }
                CELL(0, u & 3, eu, qu, el, ql, ed, qd, wIdx)
            }

            // ---- branch-free harvest: value computed unconditionally once per
            // 4-step block; single guarded store -> bare @P STG, no BSSY.
            if (u == 2) {
                float res = -((float)q[0][3] + lg2f_(e[0][3])) * LN2;
                if (harv) out[hIdx] = res;
            }

            // rotate shuffle pipeline
            shPe = shCe;  shPq = shCq;
            shCe = shNe;  shCq = shNq;
        }
    }
    #undef CELL
}

extern "C" void kernel_launch(void* const* d_in, const int* in_sizes, int n_in,
                              void* d_out, int out_size)
{
    const float* X = (const float*)d_in[0];
    const float* Y = (const float*)d_in[1];
    if (n_in >= 2 && in_sizes[0] < in_sizes[1]) {
        const float* t = X; X = Y; Y = t;
    }
    float* out = (float*)d_out;

    // 128 blocks x 128 threads: block = 4 a-values x one b-quad; warp = 4 chained pairs.
    // <=1 block per SM -> exactly 1 warp per SMSP, uniform load.
    sdtw_kernel<<<128, 128>>>(X, Y, out);
}

// round 17
// speedup vs baseline: 1.0044x; 1.0044x over previous
#include <cuda_runtime.h>

#define L2E  1.4426950408889634f
#define LN2  0.6931471805599453f
#define BIGQ (-(1 << 27))

typedef unsigned long long u64;

__device__ __forceinline__ float ex2f_(float x){ float r; asm("ex2.approx.f32 %0, %1;" : "=f"(r) : "f"(x)); return r; }
__device__ __forceinline__ float lg2f_(float x){ float r; asm("lg2.approx.f32 %0, %1;" : "=f"(r) : "f"(x)); return r; }
__device__ __forceinline__ u64 pk2(float lo, float hi){ u64 r; asm("mov.b64 %0,{%1,%2};" : "=l"(r) : "f"(lo), "f"(hi)); return r; }
__device__ __forceinline__ void upk2(float& lo, float& hi, u64 v){ asm("mov.b64 {%0,%1},%2;" : "=f"(lo), "=f"(hi) : "l"(v)); }
__device__ __forceinline__ u64 fma2(u64 a, u64 b, u64 c){ u64 r; asm("fma.rn.f32x2 %0,%1,%2,%3;" : "=l"(r) : "l"(a), "l"(b), "l"(c)); return r; }

// exact e * 2^max(dq, -126), e in [1,2), dq <= 0 (IADD3 + IMNMX + IMAD)
__device__ __forceinline__ float scl_(float e, int dq){
    int d = dq < -126 ? -126 : dq;
    return __uint_as_float(__float_as_uint(e) + (unsigned)d * 8388608u);
}

// One warp = FOUR (a,b) pairs chained in anti-phase (+128 steps each), 4 rows/thread,
// 1 warp per SMSP (128 blocks x 128 threads). Weight-domain DP: w = e*2^q.
// This round: FFMA2 dot with zero packing overhead — Y rows stored as packed
// 12-float chunks [y0..3][y4..7][nyq,0,0,0], loaded straight into u64 register
// pairs; seeds pre-packed at init. 5 FFMA2 replace FADD + 8 FFMA per cell.
__global__ __launch_bounds__(128, 1)
void sdtw_kernel(const float* __restrict__ X, const float* __restrict__ Y,
                 float* __restrict__ out)
{
    // 4 tiles, 1536 floats each. Row j of tile t:
    //   chunk c (c=0,1,2) word w at sy[t*1536 + (j&3)*384 + c*128 + (j>>2)*4 + w]
    //   chunk0/1 = y[0..7]; chunk2 = (-L2E*|y|^2, 0, 0, 0)
    __shared__ __align__(16) float sy[4 * 1536];

    const int tid  = threadIdx.x;
    const int lane = tid & 31;
    const int wid  = tid >> 5;

    const int b0 = (blockIdx.x & 3) * 4;
    const int a  = (blockIdx.x >> 2) * 4 + wid;

    for (int rep = 0; rep < 4; ++rep) {
        int gr   = tid + rep * 128;
        int tile = gr >> 7;
        int j    = gr & 127;
        const float* yrow = Y + (size_t)(b0 + tile) * 1024 + j * 8;
        float sq = 0.f;
        int base = tile * 1536 + (j & 3) * 384 + (j >> 2) * 4;
        #pragma unroll
        for (int k = 0; k < 8; ++k) {
            float vv = yrow[k];
            sq = fmaf(vv, vv, sq);
            sy[base + (k >> 2) * 128 + (k & 3)] = vv;
        }
        sy[base + 256 + 0] = sq * (-L2E);
        sy[base + 256 + 1] = 0.f;
        sy[base + 256 + 2] = 0.f;
        sy[base + 256 + 3] = 0.f;
    }

    // X packed once: xs2 = +2*L2E*x pairs; nsq2[s] = (-L2E*|x|^2, 0); xs21 = (1,0)
    u64 xs2[4][4];
    u64 nsq2[4];
    const u64 xs21 = pk2(1.0f, 0.0f);
    {
        const float* xp = X + (size_t)a * 1024 + lane * 32;
        #pragma unroll
        for (int s = 0; s < 4; ++s) {
            float acc = 0.f;
            #pragma unroll
            for (int kp = 0; kp < 4; ++kp) {
                float f0 = xp[s * 8 + 2 * kp];
                float f1 = xp[s * 8 + 2 * kp + 1];
                acc = fmaf(f0, f0, fmaf(f1, f1, acc));
                xs2[s][kp] = pk2(f0 * (2.0f * L2E), f1 * (2.0f * L2E));
            }
            nsq2[s] = pk2(acc * (-L2E), 0.f);
        }
    }
    __syncthreads();

    // DP state: mantissa e in [1,2), exponent q (int). Masked == q very negative.
    float e[2][4];
    int   q[2][4];
    #pragma unroll
    for (int s = 0; s < 4; ++s) {
        e[0][s] = 1.0f; e[1][s] = 1.0f;
        q[0][s] = BIGQ; q[1][s] = BIGQ;
    }

    // Y register pipeline: buffer (p)&3 holds row ja0(p) = p - 4*lane,
    // as 4 packed y-pairs + 1 packed (nyq,0) pair.
    u64 yp2[4][4];
    u64 ynq[4];
    #pragma unroll
    for (int b = 0; b < 4; ++b) {
        ynq[b] = 0ull;
        #pragma unroll
        for (int kp = 0; kp < 4; ++kp) yp2[b][kp] = 0ull;
    }

    const int lane4 = lane * 4;

    // prologue: buffer 0 <- row ja0(p=0) = -lane4 (wrapped; real only for lane 0)
    {
        unsigned jb = (unsigned)(-lane4) & 511u;
        int A = (int)(jb >> 7) * 1536 + (int)(jb & 3u) * 384 + (int)((jb >> 2) & 31u) * 4;
        ulonglong2 u0 = *reinterpret_cast<const ulonglong2*>(&sy[A]);
        ulonglong2 u1 = *reinterpret_cast<const ulonglong2*>(&sy[A + 128]);
        yp2[0][0] = u0.x; yp2[0][1] = u0.y; yp2[0][2] = u1.x; yp2[0][3] = u1.y;
        ynq[0] = *reinterpret_cast<const u64*>(&sy[A + 256]);
    }

    // shuffle pipeline: shC = shfl of slot3 from step p-1 (this step's s=0 "up"),
    //                   shP = shfl of slot3 from step p-2 (this step's s=0 "diag").
    float shCe = 1.0f, shPe = 1.0f;
    int   shCq = BIGQ, shPq = BIGQ;

    const int outA = a * 16 + b0;
    const bool storeLane = (lane == 31);

    // one DP cell: softmin(aligned add) * ex2(distance via 5 FFMA2), exact split
    #define CELL(S, BUF, EU, QU, EL, QL, ED, QD, WI)                                   \
    {                                                                                   \
        int qm = max(max((QU), (QL)), (QD));                                            \
        float sum = (scl_((EU), (QU) - qm) + scl_((EL), (QL) - qm))                     \
                  + scl_((ED), (QD) - qm);                                              \
        u64 acc2 = fma2(xs2[S][0], yp2[BUF][0], nsq2[S]);                               \
        acc2 = fma2(xs2[S][1], yp2[BUF][1], acc2);                                      \
        acc2 = fma2(xs2[S][2], yp2[BUF][2], acc2);                                      \
        acc2 = fma2(xs2[S][3], yp2[BUF][3], acc2);                                      \
        acc2 = fma2(xs21, ynq[BUF], acc2);                                              \
        float lo_, hi_; upk2(lo_, hi_, acc2);                                           \
        float w = sum * ex2f_(lo_ + hi_);                                               \
        unsigned wb = __float_as_uint(w);                                               \
        q[WI][S] = qm - 127 + (int)(wb >> 23);                                          \
        e[WI][S] = __uint_as_float((wb & 0x007FFFFFu) | 0x3F800000u);                   \
    }

    for (int p0 = 0; p0 < 640; p0 += 4) {
        const int j0      = p0 - lane4;
        const unsigned jc = (unsigned)j0 & 511u;
        const unsigned jn = (unsigned)(j0 + 4) & 511u;
        const int base0   = (int)(jc >> 7) * 1536 + (int)((jc >> 2) & 31u) * 4;
        const int base1   = (int)(jn >> 7) * 1536 + (int)((jn >> 2) & 31u) * 4;
        const bool bj0    = ((jc & 127u) == 0u);   // per-pair j==0 boundary: fires only at s==u
        const bool harv   = ((p0 & 127) == 124) && (p0 >= 252) && storeLane;
        const int  hIdx   = outA + ((p0 - 252) >> 7);

        #pragma unroll
        for (int u = 0; u < 4; ++u) {
            const int wIdx = u & 1;
            const int rIdx = wIdx ^ 1;

            // ---- slot 3 FIRST (reads prev2 q[wIdx][2] before slot 2 overwrites it) ----
            {
                float el = e[rIdx][3], ed = e[wIdx][2];
                int   ql, qd;
                if (u == 3) { ql = bj0 ? BIGQ : q[rIdx][3];  qd = bj0 ? BIGQ : q[wIdx][2]; }
                else        { ql = q[rIdx][3];               qd = q[wIdx][2]; }
                CELL(3, (u + 1) & 3, e[rIdx][2], q[rIdx][2], el, ql, ed, qd, wIdx)
            }

            // ---- shuffle slot3 for NEXT step, issued ~100 instr before its consumer ----
            const float shNe = __shfl_up_sync(0xffffffffu, e[wIdx][3], 1);
            const int   shNq = __shfl_up_sync(0xffffffffu, q[wIdx][3], 1);

            // ---- refill buffer (u+1)&3 (slot 3, its only pending reader, is done) ----
            {
                const int A = (u < 3) ? (base0 + (u + 1) * 384) : base1;
                const int b = (u + 1) & 3;
                ulonglong2 u0 = *reinterpret_cast<const ulonglong2*>(&sy[A]);
                ulonglong2 u1 = *reinterpret_cast<const ulonglong2*>(&sy[A + 128]);
                yp2[b][0] = u0.x; yp2[b][1] = u0.y; yp2[b][2] = u1.x; yp2[b][3] = u1.y;
                ynq[b] = *reinterpret_cast<const u64*>(&sy[A + 256]);
            }

            // ---- slots 2, 1 ----
            #pragma unroll
            for (int s = 2; s >= 1; --s) {
                float el = e[rIdx][s], ed = e[wIdx][s - 1];
                int   ql, qd;
                if (s == u) { ql = bj0 ? BIGQ : q[rIdx][s];  qd = bj0 ? BIGQ : q[wIdx][s - 1]; }
                else        { ql = q[rIdx][s];               qd = q[wIdx][s - 1]; }
                CELL(s, (u - s) & 3, e[rIdx][s - 1], q[rIdx][s - 1], el, ql, ed, qd, wIdx)
            }

            // ---- slot 0 (consumes the shuffles issued LAST step: shC/shP) ----
            {
                float eu = shCe, el, ed;
                int   qu = (lane == 0) ? BIGQ : shCq, ql, qd;
                if (u == 0) {
                    el = e[rIdx][0];  ql = bj0 ? BIGQ : q[rIdx][0];
                    if (lane == 0) { ed = 1.0f;  qd = bj0 ? 0 : BIGQ; }   // corner seed of each pair
                    else           { ed = shPe;  qd = bj0 ? BIGQ : shPq; }
                } else {
                    el = e[rIdx][0];  ql = q[rIdx][0];
                    ed = shPe;        qd = (lane == 0) ? BIGQ : shPq;
                }
                CELL(0, u & 3, eu, qu, el, ql, ed, qd, wIdx)
            }

            // ---- branch-free harvest: value computed unconditionally once per
            // 4-step block; single guarded store -> bare @P STG, no BSSY.
            if (u == 2) {
                float res = -((float)q[0][3] + lg2f_(e[0][3])) * LN2;
                if (harv) out[hIdx] = res;
            }

            // rotate shuffle pipeline
            shPe = shCe;  shPq = shCq;
            shCe = shNe;  shCq = shNq;
        }
    }
    #undef CELL
}

extern "C" void kernel_launch(void* const* d_in, const int* in_sizes, int n_in,
                              void* d_out, int out_size)
{
    const float* X = (const float*)d_in[0];
    const float* Y = (const float*)d_in[1];
    if (n_in >= 2 && in_sizes[0] < in_sizes[1]) {
        const float* t = X; X = Y; Y = t;
    }
    float* out = (float*)d_out;

    // 128 blocks x 128 threads: block = 4 a-values x one b-quad; warp = 4 chained pairs.
    // <=1 block per SM -> exactly 1 warp per SMSP, uniform load.
    sdtw_kernel<<<128, 128>>>(X, Y, out);
}